// round 5
// baseline (speedup 1.0000x reference)
#include <cuda_runtime.h>
#include <cuda_bf16.h>
#include <cstdint>

#define B_  4
#define T_  64
#define S_  256
#define E_  512
#define D_  512
#define F_  128

#define LOG2E 1.4426950408889634f
#define SCH 8
#define TT  8

// -------- scratch (device globals) --------
__device__ float g_out_hs [S_ * B_ * D_];
__device__ float g_out_fds[B_ * S_ * D_];
__device__ float g_o2p    [B_ * T_ * D_];
__device__ float g_o3p    [B_ * T_ * D_];
__device__ float g_ps1    [B_ * T_ * SCH * D_];
__device__ float g_ps2    [B_ * T_ * SCH * D_];

// ============================================================================
// Fused 4-in-1 GEMM, tf32 mma.sync, DOUBLE-BUFFERED smem pipeline.
// ============================================================================
struct Desc {
    const float *A, *W, *bias;
    float *C;
    int K, N, mode;
    int base, bncnt;
};
struct Descs { Desc d[4]; };

__device__ __forceinline__ uint32_t f2tf32(float x) {
    uint32_t r;
    asm("cvt.rna.tf32.f32 %0, %1;" : "=r"(r) : "f"(x));
    return r;
}
__device__ __forceinline__ uint4 cvt4(float4 v) {
    uint4 u;
    u.x = f2tf32(v.x); u.y = f2tf32(v.y); u.z = f2tf32(v.z); u.w = f2tf32(v.w);
    return u;
}

__global__ void __launch_bounds__(256, 3)
fused_gemm_tf32(Descs P)
{
    int bx = blockIdx.x;
    int gi;
    if      (bx >= P.d[3].base) gi = 3;
    else if (bx >= P.d[2].base) gi = 2;
    else if (bx >= P.d[1].base) gi = 1;
    else                        gi = 0;
    const Desc dsc = P.d[gi];

    int local = bx - dsc.base;
    int bm = local / dsc.bncnt;
    int bn = local - bm * dsc.bncnt;
    int m0 = bm * 64, n0 = bn * 64;
    const int K = dsc.K, N = dsc.N;

    // [2] double buffer; stride 36 -> CF fragment reads and CF uint4 stores
    __shared__ uint32_t As[2][64][36];
    __shared__ uint32_t Ws[2][64][36];

    int tid  = threadIdx.x;
    int lane = tid & 31;
    int w    = tid >> 5;
    int wm   = w & 3;
    int wn   = w >> 2;
    int lrow = tid >> 2;
    int lc8  = (tid & 3) * 8;

    int fr = lane >> 2;
    int fc = lane & 3;

    float acc[4][4];
#pragma unroll
    for (int i = 0; i < 4; i++)
#pragma unroll
        for (int j = 0; j < 4; j++) acc[i][j] = 0.f;

    const float* Abase = dsc.A + (size_t)(m0 + lrow) * K + lc8;
    const float* Wbase = dsc.W + (size_t)(n0 + lrow) * K + lc8;

    int nk = K >> 5;

    // chunk 0: load + store to buffer 0
    {
        float4 a0 = *(const float4*)(Abase);
        float4 a1 = *(const float4*)(Abase + 4);
        float4 w0 = *(const float4*)(Wbase);
        float4 w1 = *(const float4*)(Wbase + 4);
        *(uint4*)&As[0][lrow][lc8]     = cvt4(a0);
        *(uint4*)&As[0][lrow][lc8 + 4] = cvt4(a1);
        *(uint4*)&Ws[0][lrow][lc8]     = cvt4(w0);
        *(uint4*)&Ws[0][lrow][lc8 + 4] = cvt4(w1);
    }
    __syncthreads();

    for (int ks = 0; ks < nk; ks++) {
        int buf = ks & 1;

        // issue LDG for chunk ks+1 early (hidden behind MMAs below)
        float4 na0, na1, nw0, nw1;
        bool more = (ks + 1 < nk);
        if (more) {
            const float* ap = Abase + ((ks + 1) << 5);
            const float* wp = Wbase + ((ks + 1) << 5);
            na0 = *(const float4*)(ap);
            na1 = *(const float4*)(ap + 4);
            nw0 = *(const float4*)(wp);
            nw1 = *(const float4*)(wp + 4);
        }

        // consume current buffer
#pragma unroll
        for (int kq = 0; kq < 4; kq++) {
            int kc = kq * 8 + fc;
            uint32_t a0 = As[buf][wm * 16 + fr    ][kc];
            uint32_t a1 = As[buf][wm * 16 + fr + 8][kc];
            uint32_t a2 = As[buf][wm * 16 + fr    ][kc + 4];
            uint32_t a3 = As[buf][wm * 16 + fr + 8][kc + 4];
#pragma unroll
            for (int nt = 0; nt < 4; nt++) {
                uint32_t b0 = Ws[buf][wn * 32 + nt * 8 + fr][kc];
                uint32_t b1 = Ws[buf][wn * 32 + nt * 8 + fr][kc + 4];
                asm volatile(
                    "mma.sync.aligned.m16n8k8.row.col.f32.tf32.tf32.f32 "
                    "{%0,%1,%2,%3}, {%4,%5,%6,%7}, {%8,%9}, {%0,%1,%2,%3};"
                    : "+f"(acc[nt][0]), "+f"(acc[nt][1]),
                      "+f"(acc[nt][2]), "+f"(acc[nt][3])
                    : "r"(a0), "r"(a1), "r"(a2), "r"(a3), "r"(b0), "r"(b1));
            }
        }

        // fill the other buffer for chunk ks+1
        if (more) {
            int nb = buf ^ 1;
            *(uint4*)&As[nb][lrow][lc8]     = cvt4(na0);
            *(uint4*)&As[nb][lrow][lc8 + 4] = cvt4(na1);
            *(uint4*)&Ws[nb][lrow][lc8]     = cvt4(nw0);
            *(uint4*)&Ws[nb][lrow][lc8 + 4] = cvt4(nw1);
        }
        __syncthreads();
    }

    int r0 = m0 + wm * 16 + fr;
#pragma unroll
    for (int nt = 0; nt < 4; nt++) {
        int col = n0 + wn * 32 + nt * 8 + 2 * fc;
        float bb0 = dsc.bias[col];
        float bb1 = dsc.bias[col + 1];
        float v0 = tanhf(acc[nt][0] + bb0);
        float v1 = tanhf(acc[nt][1] + bb1);
        float v2 = tanhf(acc[nt][2] + bb0);
        float v3 = tanhf(acc[nt][3] + bb1);
        if (dsc.mode) { v0 *= LOG2E; v1 *= LOG2E; v2 *= LOG2E; v3 *= LOG2E; }
        *(float2*)&dsc.C[(size_t)r0       * N + col] = make_float2(v0, v1);
        *(float2*)&dsc.C[(size_t)(r0 + 8) * N + col] = make_float2(v2, v3);
    }
}

// ============================================================================
// Attention partial over S/SCH = 32 encoder positions per block.
// ============================================================================
__global__ void __launch_bounds__(128)
dual_attn_partial(const float* __restrict__ out_hs,
                  const float* __restrict__ out_fds,
                  const float* __restrict__ enc,
                  const float* __restrict__ o2p,
                  const float* __restrict__ o3p,
                  float* __restrict__ ps1,
                  float* __restrict__ ps2)
{
    int d  = blockIdx.x * 128 + threadIdx.x;
    int t0 = blockIdx.y * TT;
    int bz = blockIdx.z;
    int b  = bz >> 3;
    int sc = bz & 7;

    float o2[TT], o3[TT], s1[TT], s2[TT];
#pragma unroll
    for (int i = 0; i < TT; i++) {
        int r = b * T_ + t0 + i;
        o2[i] = o2p[r * D_ + d];
        o3[i] = o3p[r * D_ + d];
        s1[i] = 0.f;
        s2[i] = 0.f;
    }

    const int SC = S_ / SCH;   // 32
    size_t base = ((size_t)b * S_ + sc * SC) * D_ + d;

    for (int s = 0; s < SC; s += 4) {
        float hh[4], ff[4], ee[4];
#pragma unroll
        for (int u = 0; u < 4; u++) hh[u] = out_hs [base + u * D_];
#pragma unroll
        for (int u = 0; u < 4; u++) ff[u] = out_fds[base + u * D_];
#pragma unroll
        for (int u = 0; u < 4; u++) ee[u] = enc    [base + u * D_];
        base += 4 * D_;
#pragma unroll
        for (int u = 0; u < 4; u++) {
#pragma unroll
            for (int i = 0; i < TT; i++) {
                float g = fmaf(hh[u], o2[i], ff[u] * o3[i]);
                float ex;
                asm("ex2.approx.f32 %0, %1;" : "=f"(ex) : "f"(g));
                s1[i] += ex;
                s2[i] = fmaf(ex, ee[u], s2[i]);
            }
        }
    }

#pragma unroll
    for (int i = 0; i < TT; i++) {
        size_t idx = (((size_t)(b * T_ + t0 + i)) * SCH + sc) * D_ + d;
        ps1[idx] = s1[i];
        ps2[idx] = s2[i];
    }
}

// ============================================================================
// Finalize: reduce SCH partials (float4), divide, write concat (+attn).
// ============================================================================
__global__ void __launch_bounds__(128)
attn_finalize(const float* __restrict__ ps1,
              const float* __restrict__ ps2,
              const float* __restrict__ outp,
              float* __restrict__ concat,
              float* __restrict__ attn_out)
{
    int d4 = threadIdx.x * 4;
    int r  = blockIdx.z * T_ + blockIdx.y;

    size_t base = ((size_t)r * SCH) * D_ + d4;
    float4 s1 = make_float4(0, 0, 0, 0), s2 = make_float4(0, 0, 0, 0);
#pragma unroll
    for (int sc = 0; sc < SCH; sc++) {
        float4 a = *(const float4*)&ps1[base + (size_t)sc * D_];
        float4 b = *(const float4*)&ps2[base + (size_t)sc * D_];
        s1.x += a.x; s1.y += a.y; s1.z += a.z; s1.w += a.w;
        s2.x += b.x; s2.y += b.y; s2.z += b.z; s2.w += b.w;
    }
    float4 at = make_float4(s2.x / s1.x, s2.y / s1.y, s2.z / s1.z, s2.w / s1.w);
    float4 ov = *(const float4*)&outp[(size_t)r * D_ + d4];
    *(float4*)&concat[(size_t)r * (2 * D_) + d4]      = ov;
    *(float4*)&concat[(size_t)r * (2 * D_) + D_ + d4] = at;
    if (attn_out) *(float4*)&attn_out[(size_t)r * D_ + d4] = at;
}

// ============================================================================
// kernel_launch
// ============================================================================
extern "C" void kernel_launch(void* const* d_in, const int* in_sizes, int n_in,
                              void* d_out, int out_size)
{
    const float* output = (const float*)d_in[0];
    const float* enc    = (const float*)d_in[1];
    const float* z      = (const float*)d_in[2];
    const float* W1 = (const float*)d_in[3];
    const float* b1 = (const float*)d_in[4];
    const float* W2 = (const float*)d_in[5];
    const float* b2 = (const float*)d_in[6];
    const float* W3 = (const float*)d_in[7];
    const float* b3 = (const float*)d_in[8];
    const float* W4 = (const float*)d_in[9];
    const float* b4 = (const float*)d_in[10];

    float *p_hs, *p_fds, *p_o2, *p_o3, *p_s1, *p_s2;
    cudaGetSymbolAddress((void**)&p_hs,  g_out_hs);
    cudaGetSymbolAddress((void**)&p_fds, g_out_fds);
    cudaGetSymbolAddress((void**)&p_o2,  g_o2p);
    cudaGetSymbolAddress((void**)&p_o3,  g_o3p);
    cudaGetSymbolAddress((void**)&p_s1,  g_ps1);
    cudaGetSymbolAddress((void**)&p_s2,  g_ps2);

    float* concat = (float*)d_out;
    const int concat_elems = B_ * T_ * 2 * D_;
    const int attn_elems   = B_ * T_ * D_;
    float* attn_out = (out_size >= concat_elems + attn_elems)
                        ? concat + concat_elems : nullptr;

    // allow 3 blocks/SM worth of smem residency
    static bool attr_set = false;
    if (!attr_set) {
        cudaFuncSetAttribute(fused_gemm_tf32,
                             cudaFuncAttributePreferredSharedMemoryCarveout, 100);
        attr_set = true;
    }

    Descs P;
    P.d[0] = { enc,    W1, b1, p_hs,  E_, D_, 0,   0, D_ / 64 };
    P.d[1] = { z,      W3, b3, p_fds, F_, D_, 0, 128, D_ / 64 };
    P.d[2] = { output, W2, b2, p_o2,  D_, D_, 1, 256, D_ / 64 };
    P.d[3] = { output, W4, b4, p_o3,  D_, D_, 1, 288, D_ / 64 };

    fused_gemm_tf32<<<320, 256>>>(P);

    dual_attn_partial<<<dim3(D_ / 128, T_ / TT, B_ * SCH), 128>>>(
        p_hs, p_fds, enc, p_o2, p_o3, p_s1, p_s2);

    attn_finalize<<<dim3(1, T_, B_), 128>>>(
        p_s1, p_s2, output, concat, attn_out);
}

// round 6
// speedup vs baseline: 1.0398x; 1.0398x over previous
#include <cuda_runtime.h>
#include <cuda_bf16.h>
#include <cstdint>

#define B_  4
#define T_  64
#define S_  256
#define E_  512
#define D_  512
#define F_  128

#define LOG2E 1.4426950408889634f
#define SCH 8
#define TT  8

// GEMM tile config
#define BM 128
#define BN 64
#define STRIDE 36
#define STAGE_WORDS ((BM + BN) * STRIDE)   // 6912 words = 27648 B
#define NSTAGE 3
#define GEMM_SMEM_BYTES (STAGE_WORDS * NSTAGE * 4)   // 82944

// -------- scratch (device globals) --------
__device__ float g_out_hs [S_ * B_ * D_];
__device__ float g_out_fds[B_ * S_ * D_];
__device__ float g_o2p    [B_ * T_ * D_];
__device__ float g_o3p    [B_ * T_ * D_];
__device__ float g_ps1    [B_ * T_ * SCH * D_];
__device__ float g_ps2    [B_ * T_ * SCH * D_];

struct Desc {
    const float *A, *W, *bias;
    float *C;
    int K, N, mode;
    int base, bncnt;
};
struct Descs { Desc d[4]; };

__device__ __forceinline__ uint32_t f2tf32(uint32_t raw) {
    uint32_t r;
    asm("cvt.rna.tf32.f32 %0, %1;" : "=r"(r) : "f"(__uint_as_float(raw)));
    return r;
}
__device__ __forceinline__ uint32_t smem_u32(const void* p) {
    uint32_t a;
    asm("{ .reg .u64 t; cvta.to.shared.u64 t, %1; cvt.u32.u64 %0, t; }"
        : "=r"(a) : "l"(p));
    return a;
}
__device__ __forceinline__ void cp16(uint32_t dst, const void* src) {
    asm volatile("cp.async.cg.shared.global [%0], [%1], 16;"
                 :: "r"(dst), "l"(src));
}

// ============================================================================
// Fused 4-in-1 GEMM: 128x64 block, 8 warps (4m x 2n), 32x32 warp tiles,
// tf32 mma.sync, cp.async 3-stage pipeline, rna convert at fragment load.
// ============================================================================
__global__ void __launch_bounds__(256, 2)
fused_gemm_tf32(Descs P)
{
    extern __shared__ uint32_t sm[];

    int bx = blockIdx.x;
    int gi;
    if      (bx >= P.d[3].base) gi = 3;
    else if (bx >= P.d[2].base) gi = 2;
    else if (bx >= P.d[1].base) gi = 1;
    else                        gi = 0;
    const Desc dsc = P.d[gi];

    int local = bx - dsc.base;
    int bm = local / dsc.bncnt;
    int bn = local - bm * dsc.bncnt;
    int m0 = bm * BM, n0 = bn * BN;
    const int K = dsc.K, N = dsc.N;
    const int nk = K >> 5;

    int tid  = threadIdx.x;
    int lane = tid & 31;
    int w    = tid >> 5;
    int wm   = w & 3;          // 0..3 : 32-row group
    int wn   = w >> 2;         // 0..1 : 32-col group
    int fr   = lane >> 2;      // 0..7
    int fc   = lane & 3;       // 0..3

    // cp.async mapping: 8 threads per 32-float row segment
    int arow = tid >> 3;           // 0..31
    int acol = (tid & 7) * 4;      // word col 0,4,...,28

    uint32_t sbase = smem_u32(sm);
    const float* Ag = dsc.A + (size_t)(m0 + arow) * K + acol;
    const float* Wg = dsc.W + (size_t)(n0 + arow) * K + acol;

    // issue one stage (BM x 32 of A, BN x 32 of W) via cp.async
    auto issue = [&](int ks, int stage) {
        uint32_t sb = sbase + (uint32_t)(stage * STAGE_WORDS) * 4u;
        int koff = ks << 5;
#pragma unroll
        for (int i = 0; i < 4; i++)
            cp16(sb + ((arow + 32 * i) * STRIDE + acol) * 4u,
                 Ag + (size_t)(32 * i) * K + koff);
#pragma unroll
        for (int i = 0; i < 2; i++)
            cp16(sb + ((BM + arow + 32 * i) * STRIDE + acol) * 4u,
                 Wg + (size_t)(32 * i) * K + koff);
        asm volatile("cp.async.commit_group;" ::: "memory");
    };

    float acc[2][4][4];
#pragma unroll
    for (int a = 0; a < 2; a++)
#pragma unroll
        for (int b = 0; b < 4; b++)
#pragma unroll
            for (int c = 0; c < 4; c++) acc[a][b][c] = 0.f;

    issue(0, 0);
    issue(1, 1);

    for (int ks = 0; ks < nk; ks++) {
        if (ks + 1 < nk) asm volatile("cp.async.wait_group 1;" ::: "memory");
        else             asm volatile("cp.async.wait_group 0;" ::: "memory");
        __syncthreads();

        if (ks + 2 < nk) issue(ks + 2, (ks + 2) % 3);

        const uint32_t* Abuf = sm + (ks % 3) * STAGE_WORDS;
        const uint32_t* Wbuf = Abuf + BM * STRIDE;

#pragma unroll
        for (int kq = 0; kq < 4; kq++) {
            int kc = kq * 8 + fc;
            uint32_t a[2][4];
#pragma unroll
            for (int mf = 0; mf < 2; mf++) {
                int r = wm * 32 + mf * 16 + fr;
                a[mf][0] = f2tf32(Abuf[ r      * STRIDE + kc    ]);
                a[mf][1] = f2tf32(Abuf[(r + 8) * STRIDE + kc    ]);
                a[mf][2] = f2tf32(Abuf[ r      * STRIDE + kc + 4]);
                a[mf][3] = f2tf32(Abuf[(r + 8) * STRIDE + kc + 4]);
            }
#pragma unroll
            for (int nf = 0; nf < 4; nf++) {
                int rw = wn * 32 + nf * 8 + fr;
                uint32_t b0 = f2tf32(Wbuf[rw * STRIDE + kc    ]);
                uint32_t b1 = f2tf32(Wbuf[rw * STRIDE + kc + 4]);
#pragma unroll
                for (int mf = 0; mf < 2; mf++) {
                    asm volatile(
                        "mma.sync.aligned.m16n8k8.row.col.f32.tf32.tf32.f32 "
                        "{%0,%1,%2,%3}, {%4,%5,%6,%7}, {%8,%9}, {%0,%1,%2,%3};"
                        : "+f"(acc[mf][nf][0]), "+f"(acc[mf][nf][1]),
                          "+f"(acc[mf][nf][2]), "+f"(acc[mf][nf][3])
                        : "r"(a[mf][0]), "r"(a[mf][1]), "r"(a[mf][2]),
                          "r"(a[mf][3]), "r"(b0), "r"(b1));
                }
            }
        }
    }

    // epilogue: bias + tanh (+ *log2e)
#pragma unroll
    for (int mf = 0; mf < 2; mf++) {
        int r0 = m0 + wm * 32 + mf * 16 + fr;
#pragma unroll
        for (int nf = 0; nf < 4; nf++) {
            int col = n0 + wn * 32 + nf * 8 + 2 * fc;
            float bb0 = dsc.bias[col];
            float bb1 = dsc.bias[col + 1];
            float v0 = tanhf(acc[mf][nf][0] + bb0);
            float v1 = tanhf(acc[mf][nf][1] + bb1);
            float v2 = tanhf(acc[mf][nf][2] + bb0);
            float v3 = tanhf(acc[mf][nf][3] + bb1);
            if (dsc.mode) { v0 *= LOG2E; v1 *= LOG2E; v2 *= LOG2E; v3 *= LOG2E; }
            *(float2*)&dsc.C[(size_t)r0       * N + col] = make_float2(v0, v1);
            *(float2*)&dsc.C[(size_t)(r0 + 8) * N + col] = make_float2(v2, v3);
        }
    }
}

// ============================================================================
// Attention partial over S/SCH = 32 encoder positions per block.
// ============================================================================
__global__ void __launch_bounds__(128)
dual_attn_partial(const float* __restrict__ out_hs,
                  const float* __restrict__ out_fds,
                  const float* __restrict__ enc,
                  const float* __restrict__ o2p,
                  const float* __restrict__ o3p,
                  float* __restrict__ ps1,
                  float* __restrict__ ps2)
{
    int d  = blockIdx.x * 128 + threadIdx.x;
    int t0 = blockIdx.y * TT;
    int bz = blockIdx.z;
    int b  = bz >> 3;
    int sc = bz & 7;

    float o2[TT], o3[TT], s1[TT], s2[TT];
#pragma unroll
    for (int i = 0; i < TT; i++) {
        int r = b * T_ + t0 + i;
        o2[i] = o2p[r * D_ + d];
        o3[i] = o3p[r * D_ + d];
        s1[i] = 0.f;
        s2[i] = 0.f;
    }

    const int SC = S_ / SCH;   // 32
    size_t base = ((size_t)b * S_ + sc * SC) * D_ + d;

    for (int s = 0; s < SC; s += 4) {
        float hh[4], ff[4], ee[4];
#pragma unroll
        for (int u = 0; u < 4; u++) hh[u] = out_hs [base + u * D_];
#pragma unroll
        for (int u = 0; u < 4; u++) ff[u] = out_fds[base + u * D_];
#pragma unroll
        for (int u = 0; u < 4; u++) ee[u] = enc    [base + u * D_];
        base += 4 * D_;
#pragma unroll
        for (int u = 0; u < 4; u++) {
#pragma unroll
            for (int i = 0; i < TT; i++) {
                float g = fmaf(hh[u], o2[i], ff[u] * o3[i]);
                float ex;
                asm("ex2.approx.f32 %0, %1;" : "=f"(ex) : "f"(g));
                s1[i] += ex;
                s2[i] = fmaf(ex, ee[u], s2[i]);
            }
        }
    }

#pragma unroll
    for (int i = 0; i < TT; i++) {
        size_t idx = (((size_t)(b * T_ + t0 + i)) * SCH + sc) * D_ + d;
        ps1[idx] = s1[i];
        ps2[idx] = s2[i];
    }
}

// ============================================================================
// Finalize: reduce SCH partials (float4), divide, write concat (+attn).
// ============================================================================
__global__ void __launch_bounds__(128)
attn_finalize(const float* __restrict__ ps1,
              const float* __restrict__ ps2,
              const float* __restrict__ outp,
              float* __restrict__ concat,
              float* __restrict__ attn_out)
{
    int d4 = threadIdx.x * 4;
    int r  = blockIdx.z * T_ + blockIdx.y;

    size_t base = ((size_t)r * SCH) * D_ + d4;
    float4 s1 = make_float4(0, 0, 0, 0), s2 = make_float4(0, 0, 0, 0);
#pragma unroll
    for (int sc = 0; sc < SCH; sc++) {
        float4 a = *(const float4*)&ps1[base + (size_t)sc * D_];
        float4 b = *(const float4*)&ps2[base + (size_t)sc * D_];
        s1.x += a.x; s1.y += a.y; s1.z += a.z; s1.w += a.w;
        s2.x += b.x; s2.y += b.y; s2.z += b.z; s2.w += b.w;
    }
    float4 at = make_float4(s2.x / s1.x, s2.y / s1.y, s2.z / s1.z, s2.w / s1.w);
    float4 ov = *(const float4*)&outp[(size_t)r * D_ + d4];
    *(float4*)&concat[(size_t)r * (2 * D_) + d4]      = ov;
    *(float4*)&concat[(size_t)r * (2 * D_) + D_ + d4] = at;
    if (attn_out) *(float4*)&attn_out[(size_t)r * D_ + d4] = at;
}

// ============================================================================
// kernel_launch
// ============================================================================
extern "C" void kernel_launch(void* const* d_in, const int* in_sizes, int n_in,
                              void* d_out, int out_size)
{
    const float* output = (const float*)d_in[0];
    const float* enc    = (const float*)d_in[1];
    const float* z      = (const float*)d_in[2];
    const float* W1 = (const float*)d_in[3];
    const float* b1 = (const float*)d_in[4];
    const float* W2 = (const float*)d_in[5];
    const float* b2 = (const float*)d_in[6];
    const float* W3 = (const float*)d_in[7];
    const float* b3 = (const float*)d_in[8];
    const float* W4 = (const float*)d_in[9];
    const float* b4 = (const float*)d_in[10];

    float *p_hs, *p_fds, *p_o2, *p_o3, *p_s1, *p_s2;
    cudaGetSymbolAddress((void**)&p_hs,  g_out_hs);
    cudaGetSymbolAddress((void**)&p_fds, g_out_fds);
    cudaGetSymbolAddress((void**)&p_o2,  g_o2p);
    cudaGetSymbolAddress((void**)&p_o3,  g_o3p);
    cudaGetSymbolAddress((void**)&p_s1,  g_ps1);
    cudaGetSymbolAddress((void**)&p_s2,  g_ps2);

    float* concat = (float*)d_out;
    const int concat_elems = B_ * T_ * 2 * D_;
    const int attn_elems   = B_ * T_ * D_;
    float* attn_out = (out_size >= concat_elems + attn_elems)
                        ? concat + concat_elems : nullptr;

    cudaFuncSetAttribute(fused_gemm_tf32,
                         cudaFuncAttributeMaxDynamicSharedMemorySize,
                         GEMM_SMEM_BYTES);

    // blocks: lin1 (1024/128)x8=64, lin3 64, lin2 (256/128)x8=16, lin4 16
    Descs P;
    P.d[0] = { enc,    W1, b1, p_hs,  E_, D_, 0,   0, D_ / BN };
    P.d[1] = { z,      W3, b3, p_fds, F_, D_, 0,  64, D_ / BN };
    P.d[2] = { output, W2, b2, p_o2,  D_, D_, 1, 128, D_ / BN };
    P.d[3] = { output, W4, b4, p_o3,  D_, D_, 1, 144, D_ / BN };

    fused_gemm_tf32<<<160, 256, GEMM_SMEM_BYTES>>>(P);

    dual_attn_partial<<<dim3(D_ / 128, T_ / TT, B_ * SCH), 128>>>(
        p_hs, p_fds, enc, p_o2, p_o3, p_s1, p_s2);

    attn_finalize<<<dim3(1, T_, B_), 128>>>(
        p_s1, p_s2, output, concat, attn_out);
}

// round 7
// speedup vs baseline: 1.1039x; 1.0616x over previous
#include <cuda_runtime.h>
#include <cuda_bf16.h>
#include <cstdint>

#define B_  4
#define T_  64
#define S_  256
#define E_  512
#define D_  512
#define F_  128

#define LOG2E 1.4426950408889634f
#define SCH 8
#define TT  8

// GEMM tile config
#define BM 128
#define BN 64
#define STRIDE 36
#define STAGE_WORDS ((BM + BN) * STRIDE)          // 6912 words
#define GEMM_SMEM_BYTES (STAGE_WORDS * 2 * 4)     // 55296 B (double buffer)

// -------- scratch (device globals) --------
__device__ float g_out_hs [S_ * B_ * D_];
__device__ float g_out_fds[B_ * S_ * D_];
__device__ float g_o2p    [B_ * T_ * D_];
__device__ float g_o3p    [B_ * T_ * D_];
__device__ float g_ps1    [B_ * T_ * SCH * D_];
__device__ float g_ps2    [B_ * T_ * SCH * D_];

struct Desc {
    const float *A, *W, *bias;
    float *C;
    int K, N, mode;
    int base, bncnt;
};
struct Descs { Desc d[4]; };

__device__ __forceinline__ uint32_t f2tf32(float x) {
    uint32_t r;
    asm("cvt.rna.tf32.f32 %0, %1;" : "=r"(r) : "f"(x));
    return r;
}
__device__ __forceinline__ uint4 cvt4(float4 v) {
    uint4 u;
    u.x = f2tf32(v.x); u.y = f2tf32(v.y); u.z = f2tf32(v.z); u.w = f2tf32(v.w);
    return u;
}
__device__ __forceinline__ uint32_t smem_u32(const void* p) {
    uint32_t a;
    asm("{ .reg .u64 t; cvta.to.shared.u64 t, %1; cvt.u32.u64 %0, t; }"
        : "=r"(a) : "l"(p));
    return a;
}

// ============================================================================
// Fused 4-in-1 GEMM: 128x64 block, 8 warps (4m x 2n), 32x32 warp tiles,
// tf32 mma.sync + ldmatrix fragment loads, cvt@STS, double-buffered smem.
// ============================================================================
__global__ void __launch_bounds__(256)
fused_gemm_tf32(Descs P)
{
    extern __shared__ uint32_t sm[];

    int bx = blockIdx.x;
    int gi;
    if      (bx >= P.d[3].base) gi = 3;
    else if (bx >= P.d[2].base) gi = 2;
    else if (bx >= P.d[1].base) gi = 1;
    else                        gi = 0;
    const Desc dsc = P.d[gi];

    int local = bx - dsc.base;
    int bm = local / dsc.bncnt;
    int bn = local - bm * dsc.bncnt;
    int m0 = bm * BM, n0 = bn * BN;
    const int K = dsc.K, N = dsc.N;
    const int nk = K >> 5;

    int tid  = threadIdx.x;
    int lane = tid & 31;
    int w    = tid >> 5;
    int wm   = w & 3;           // 32-row group
    int wn   = w >> 2;          // 32-col group
    int fr   = lane >> 2;
    int fc   = lane & 3;

    // global-load mapping: 8 threads per 32-word row segment
    int arow = tid >> 3;            // 0..31
    int acol = (tid & 7) * 4;       // 0,4,...,28

    // ldmatrix per-lane tile-row mapping
    int g    = lane >> 3;
    int trow = (g & 1) * 8 + (lane & 7);   // 0..15
    int tcol = (g >> 1) * 4;               // 0 or 4 (words)

    uint32_t sbase = smem_u32(sm);
    const uint32_t SB = STAGE_WORDS * 4u;  // stage stride bytes

    uint32_t a_lm = sbase + (uint32_t)(((wm * 32 + trow) * STRIDE + tcol) * 4);
    uint32_t w_lm = sbase + (uint32_t)(((BM + wn * 32 + trow) * STRIDE + tcol) * 4);

    const float* Ag = dsc.A + (size_t)(m0 + arow) * K + acol;
    const float* Wg = dsc.W + (size_t)(n0 + arow) * K + acol;

    float acc[2][4][4];
#pragma unroll
    for (int a = 0; a < 2; a++)
#pragma unroll
        for (int b = 0; b < 4; b++)
#pragma unroll
            for (int c = 0; c < 4; c++) acc[a][b][c] = 0.f;

    // prologue: chunk 0 -> buffer 0
    {
        float4 av[4], wv[2];
#pragma unroll
        for (int i = 0; i < 4; i++) av[i] = *(const float4*)(Ag + (size_t)(32 * i) * K);
#pragma unroll
        for (int i = 0; i < 2; i++) wv[i] = *(const float4*)(Wg + (size_t)(32 * i) * K);
#pragma unroll
        for (int i = 0; i < 4; i++)
            *(uint4*)&sm[(arow + 32 * i) * STRIDE + acol] = cvt4(av[i]);
#pragma unroll
        for (int i = 0; i < 2; i++)
            *(uint4*)&sm[(BM + arow + 32 * i) * STRIDE + acol] = cvt4(wv[i]);
    }
    __syncthreads();

    for (int ks = 0; ks < nk; ks++) {
        int buf = ks & 1;
        bool more = (ks + 1 < nk);

        // prefetch chunk ks+1 into registers (hidden behind MMAs)
        float4 av[4], wv[2];
        if (more) {
            int koff = (ks + 1) << 5;
#pragma unroll
            for (int i = 0; i < 4; i++)
                av[i] = *(const float4*)(Ag + (size_t)(32 * i) * K + koff);
#pragma unroll
            for (int i = 0; i < 2; i++)
                wv[i] = *(const float4*)(Wg + (size_t)(32 * i) * K + koff);
        }

        // consume current buffer via ldmatrix + mma
        uint32_t abase = a_lm + buf * SB;
        uint32_t wbase = w_lm + buf * SB;
#pragma unroll
        for (int kq = 0; kq < 4; kq++) {
            uint32_t a[2][4];
#pragma unroll
            for (int mf = 0; mf < 2; mf++) {
                uint32_t ad = abase + (uint32_t)((mf * 16 * STRIDE + kq * 8) * 4);
                asm volatile(
                    "ldmatrix.sync.aligned.m8n8.x4.shared.b16 {%0,%1,%2,%3}, [%4];"
                    : "=r"(a[mf][0]), "=r"(a[mf][1]), "=r"(a[mf][2]), "=r"(a[mf][3])
                    : "r"(ad));
            }
            uint32_t b[4][2];
#pragma unroll
            for (int np = 0; np < 2; np++) {
                uint32_t r0, r1, r2, r3;
                uint32_t wd = wbase + (uint32_t)((np * 16 * STRIDE + kq * 8) * 4);
                asm volatile(
                    "ldmatrix.sync.aligned.m8n8.x4.shared.b16 {%0,%1,%2,%3}, [%4];"
                    : "=r"(r0), "=r"(r1), "=r"(r2), "=r"(r3)
                    : "r"(wd));
                b[2 * np][0] = r0; b[2 * np + 1][0] = r1;
                b[2 * np][1] = r2; b[2 * np + 1][1] = r3;
            }
#pragma unroll
            for (int nf = 0; nf < 4; nf++)
#pragma unroll
                for (int mf = 0; mf < 2; mf++) {
                    asm volatile(
                        "mma.sync.aligned.m16n8k8.row.col.f32.tf32.tf32.f32 "
                        "{%0,%1,%2,%3}, {%4,%5,%6,%7}, {%8,%9}, {%0,%1,%2,%3};"
                        : "+f"(acc[mf][nf][0]), "+f"(acc[mf][nf][1]),
                          "+f"(acc[mf][nf][2]), "+f"(acc[mf][nf][3])
                        : "r"(a[mf][0]), "r"(a[mf][1]), "r"(a[mf][2]),
                          "r"(a[mf][3]), "r"(b[nf][0]), "r"(b[nf][1]));
                }
        }

        // store next chunk into the other buffer
        if (more) {
            uint32_t* dst = sm + (buf ^ 1) * STAGE_WORDS;
#pragma unroll
            for (int i = 0; i < 4; i++)
                *(uint4*)&dst[(arow + 32 * i) * STRIDE + acol] = cvt4(av[i]);
#pragma unroll
            for (int i = 0; i < 2; i++)
                *(uint4*)&dst[(BM + arow + 32 * i) * STRIDE + acol] = cvt4(wv[i]);
        }
        __syncthreads();
    }

    // epilogue: bias + tanh (+ *log2e)
#pragma unroll
    for (int mf = 0; mf < 2; mf++) {
        int r0 = m0 + wm * 32 + mf * 16 + fr;
#pragma unroll
        for (int nf = 0; nf < 4; nf++) {
            int col = n0 + wn * 32 + nf * 8 + 2 * fc;
            float bb0 = dsc.bias[col];
            float bb1 = dsc.bias[col + 1];
            float v0 = tanhf(acc[mf][nf][0] + bb0);
            float v1 = tanhf(acc[mf][nf][1] + bb1);
            float v2 = tanhf(acc[mf][nf][2] + bb0);
            float v3 = tanhf(acc[mf][nf][3] + bb1);
            if (dsc.mode) { v0 *= LOG2E; v1 *= LOG2E; v2 *= LOG2E; v3 *= LOG2E; }
            *(float2*)&dsc.C[(size_t)r0       * N + col] = make_float2(v0, v1);
            *(float2*)&dsc.C[(size_t)(r0 + 8) * N + col] = make_float2(v2, v3);
        }
    }
}

// ============================================================================
// Attention partial over S/SCH = 32 encoder positions per block.
// ============================================================================
__global__ void __launch_bounds__(128)
dual_attn_partial(const float* __restrict__ out_hs,
                  const float* __restrict__ out_fds,
                  const float* __restrict__ enc,
                  const float* __restrict__ o2p,
                  const float* __restrict__ o3p,
                  float* __restrict__ ps1,
                  float* __restrict__ ps2)
{
    int d  = blockIdx.x * 128 + threadIdx.x;
    int t0 = blockIdx.y * TT;
    int bz = blockIdx.z;
    int b  = bz >> 3;
    int sc = bz & 7;

    float o2[TT], o3[TT], s1[TT], s2[TT];
#pragma unroll
    for (int i = 0; i < TT; i++) {
        int r = b * T_ + t0 + i;
        o2[i] = o2p[r * D_ + d];
        o3[i] = o3p[r * D_ + d];
        s1[i] = 0.f;
        s2[i] = 0.f;
    }

    const int SC = S_ / SCH;   // 32
    size_t base = ((size_t)b * S_ + sc * SC) * D_ + d;

    for (int s = 0; s < SC; s += 4) {
        float hh[4], ff[4], ee[4];
#pragma unroll
        for (int u = 0; u < 4; u++) hh[u] = out_hs [base + u * D_];
#pragma unroll
        for (int u = 0; u < 4; u++) ff[u] = out_fds[base + u * D_];
#pragma unroll
        for (int u = 0; u < 4; u++) ee[u] = enc    [base + u * D_];
        base += 4 * D_;
#pragma unroll
        for (int u = 0; u < 4; u++) {
#pragma unroll
            for (int i = 0; i < TT; i++) {
                float g = fmaf(hh[u], o2[i], ff[u] * o3[i]);
                float ex;
                asm("ex2.approx.f32 %0, %1;" : "=f"(ex) : "f"(g));
                s1[i] += ex;
                s2[i] = fmaf(ex, ee[u], s2[i]);
            }
        }
    }

#pragma unroll
    for (int i = 0; i < TT; i++) {
        size_t idx = (((size_t)(b * T_ + t0 + i)) * SCH + sc) * D_ + d;
        ps1[idx] = s1[i];
        ps2[idx] = s2[i];
    }
}

// ============================================================================
// Finalize: reduce SCH partials (float4), divide, write concat (+attn).
// ============================================================================
__global__ void __launch_bounds__(128)
attn_finalize(const float* __restrict__ ps1,
              const float* __restrict__ ps2,
              const float* __restrict__ outp,
              float* __restrict__ concat,
              float* __restrict__ attn_out)
{
    int d4 = threadIdx.x * 4;
    int r  = blockIdx.z * T_ + blockIdx.y;

    size_t base = ((size_t)r * SCH) * D_ + d4;
    float4 s1 = make_float4(0, 0, 0, 0), s2 = make_float4(0, 0, 0, 0);
#pragma unroll
    for (int sc = 0; sc < SCH; sc++) {
        float4 a = *(const float4*)&ps1[base + (size_t)sc * D_];
        float4 b = *(const float4*)&ps2[base + (size_t)sc * D_];
        s1.x += a.x; s1.y += a.y; s1.z += a.z; s1.w += a.w;
        s2.x += b.x; s2.y += b.y; s2.z += b.z; s2.w += b.w;
    }
    float4 at = make_float4(s2.x / s1.x, s2.y / s1.y, s2.z / s1.z, s2.w / s1.w);
    float4 ov = *(const float4*)&outp[(size_t)r * D_ + d4];
    *(float4*)&concat[(size_t)r * (2 * D_) + d4]      = ov;
    *(float4*)&concat[(size_t)r * (2 * D_) + D_ + d4] = at;
    if (attn_out) *(float4*)&attn_out[(size_t)r * D_ + d4] = at;
}

// ============================================================================
// kernel_launch
// ============================================================================
extern "C" void kernel_launch(void* const* d_in, const int* in_sizes, int n_in,
                              void* d_out, int out_size)
{
    const float* output = (const float*)d_in[0];
    const float* enc    = (const float*)d_in[1];
    const float* z      = (const float*)d_in[2];
    const float* W1 = (const float*)d_in[3];
    const float* b1 = (const float*)d_in[4];
    const float* W2 = (const float*)d_in[5];
    const float* b2 = (const float*)d_in[6];
    const float* W3 = (const float*)d_in[7];
    const float* b3 = (const float*)d_in[8];
    const float* W4 = (const float*)d_in[9];
    const float* b4 = (const float*)d_in[10];

    float *p_hs, *p_fds, *p_o2, *p_o3, *p_s1, *p_s2;
    cudaGetSymbolAddress((void**)&p_hs,  g_out_hs);
    cudaGetSymbolAddress((void**)&p_fds, g_out_fds);
    cudaGetSymbolAddress((void**)&p_o2,  g_o2p);
    cudaGetSymbolAddress((void**)&p_o3,  g_o3p);
    cudaGetSymbolAddress((void**)&p_s1,  g_ps1);
    cudaGetSymbolAddress((void**)&p_s2,  g_ps2);

    float* concat = (float*)d_out;
    const int concat_elems = B_ * T_ * 2 * D_;
    const int attn_elems   = B_ * T_ * D_;
    float* attn_out = (out_size >= concat_elems + attn_elems)
                        ? concat + concat_elems : nullptr;

    cudaFuncSetAttribute(fused_gemm_tf32,
                         cudaFuncAttributeMaxDynamicSharedMemorySize,
                         GEMM_SMEM_BYTES);

    // blocks: lin1 (1024/128)x8=64, lin3 64, lin2 2x8=16, lin4 16 -> 160
    Descs P;
    P.d[0] = { enc,    W1, b1, p_hs,  E_, D_, 0,   0, D_ / BN };
    P.d[1] = { z,      W3, b3, p_fds, F_, D_, 0,  64, D_ / BN };
    P.d[2] = { output, W2, b2, p_o2,  D_, D_, 1, 128, D_ / BN };
    P.d[3] = { output, W4, b4, p_o3,  D_, D_, 1, 144, D_ / BN };

    fused_gemm_tf32<<<160, 256, GEMM_SMEM_BYTES>>>(P);

    dual_attn_partial<<<dim3(D_ / 128, T_ / TT, B_ * SCH), 128>>>(
        p_hs, p_fds, enc, p_o2, p_o3, p_s1, p_s2);

    attn_finalize<<<dim3(1, T_, B_), 128>>>(
        p_s1, p_s2, output, concat, attn_out);
}

// round 8
// speedup vs baseline: 1.2664x; 1.1472x over previous
#include <cuda_runtime.h>
#include <cuda_bf16.h>
#include <cstdint>

#define B_  4
#define T_  64
#define S_  256
#define E_  512
#define D_  512
#define F_  128

#define LOG2E 1.4426950408889634f
#define SCH 8
#define TT  8

// GEMM tile config
#define BM 128
#define BN 64
#define STRIDE 36
#define STAGE_WORDS ((BM + BN) * STRIDE)          // 6912 words
#define GEMM_SMEM_BYTES (STAGE_WORDS * 2 * 4)     // 55296 B (double buffer)

// -------- scratch (device globals) --------
__device__ float g_out_hs [S_ * B_ * D_];
__device__ float g_out_fds[B_ * S_ * D_];
__device__ float g_o2p    [B_ * T_ * D_];
__device__ float g_o3p    [B_ * T_ * D_];
__device__ float g_ps1    [B_ * T_ * SCH * D_];
__device__ float g_ps2    [B_ * T_ * SCH * D_];

struct Desc {
    const float *A, *W, *bias;
    float *C;
    int K, N, mode;
    int base, bncnt;
};
struct Descs { Desc d[4]; };

__device__ __forceinline__ uint32_t f2tf32(float x) {
    uint32_t r;
    asm("cvt.rna.tf32.f32 %0, %1;" : "=r"(r) : "f"(x));
    return r;
}
__device__ __forceinline__ uint4 cvt4(float4 v) {
    uint4 u;
    u.x = f2tf32(v.x); u.y = f2tf32(v.y); u.z = f2tf32(v.z); u.w = f2tf32(v.w);
    return u;
}
__device__ __forceinline__ uint32_t smem_u32(const void* p) {
    uint32_t a;
    asm("{ .reg .u64 t; cvta.to.shared.u64 t, %1; cvt.u32.u64 %0, t; }"
        : "=r"(a) : "l"(p));
    return a;
}

// ============================================================================
// Fused 4-in-1 GEMM: 128x64 block, 8 warps (4m x 2n), 32x32 warp tiles,
// tf32 mma.sync + ldmatrix, cvt@STS, double-buffered smem,
// register prefetch DISTANCE 2. Light (K=128) blocks placed LAST in grid.
// ============================================================================
__global__ void __launch_bounds__(256)
fused_gemm_tf32(Descs P)
{
    extern __shared__ uint32_t sm[];

    int bx = blockIdx.x;
    int gi;
    if      (bx >= P.d[3].base) gi = 3;
    else if (bx >= P.d[2].base) gi = 2;
    else if (bx >= P.d[1].base) gi = 1;
    else                        gi = 0;
    const Desc dsc = P.d[gi];

    int local = bx - dsc.base;
    int bm = local / dsc.bncnt;
    int bn = local - bm * dsc.bncnt;
    int m0 = bm * BM, n0 = bn * BN;
    const int K = dsc.K, N = dsc.N;
    const int nk = K >> 5;

    int tid  = threadIdx.x;
    int lane = tid & 31;
    int w    = tid >> 5;
    int wm   = w & 3;
    int wn   = w >> 2;
    int fr   = lane >> 2;
    int fc   = lane & 3;

    // global-load mapping: 8 threads per 32-word row segment
    int arow = tid >> 3;
    int acol = (tid & 7) * 4;

    // ldmatrix per-lane tile-row mapping
    int g    = lane >> 3;
    int trow = (g & 1) * 8 + (lane & 7);
    int tcol = (g >> 1) * 4;

    uint32_t sbase = smem_u32(sm);
    const uint32_t SB = STAGE_WORDS * 4u;

    uint32_t a_lm = sbase + (uint32_t)(((wm * 32 + trow) * STRIDE + tcol) * 4);
    uint32_t w_lm = sbase + (uint32_t)(((BM + wn * 32 + trow) * STRIDE + tcol) * 4);

    const float* Ag = dsc.A + (size_t)(m0 + arow) * K + acol;
    const float* Wg = dsc.W + (size_t)(n0 + arow) * K + acol;

    float acc[2][4][4];
#pragma unroll
    for (int a = 0; a < 2; a++)
#pragma unroll
        for (int b = 0; b < 4; b++)
#pragma unroll
            for (int c = 0; c < 4; c++) acc[a][b][c] = 0.f;

    // prologue: chunk 0 -> buffer 0 directly; chunk 1 -> registers
    float4 av[4], wv[2];
    {
        float4 t0[4], t1[2];
#pragma unroll
        for (int i = 0; i < 4; i++) t0[i] = *(const float4*)(Ag + (size_t)(32 * i) * K);
#pragma unroll
        for (int i = 0; i < 2; i++) t1[i] = *(const float4*)(Wg + (size_t)(32 * i) * K);
#pragma unroll
        for (int i = 0; i < 4; i++)
            *(uint4*)&sm[(arow + 32 * i) * STRIDE + acol] = cvt4(t0[i]);
#pragma unroll
        for (int i = 0; i < 2; i++)
            *(uint4*)&sm[(BM + arow + 32 * i) * STRIDE + acol] = cvt4(t1[i]);
    }
    if (nk > 1) {
#pragma unroll
        for (int i = 0; i < 4; i++)
            av[i] = *(const float4*)(Ag + (size_t)(32 * i) * K + 32);
#pragma unroll
        for (int i = 0; i < 2; i++)
            wv[i] = *(const float4*)(Wg + (size_t)(32 * i) * K + 32);
    }
    __syncthreads();

    for (int ks = 0; ks < nk; ks++) {
        int buf = ks & 1;

        // store chunk ks+1 (held in registers since last iter) into other buffer
        if (ks + 1 < nk) {
            uint32_t* dst = sm + (buf ^ 1) * STAGE_WORDS;
#pragma unroll
            for (int i = 0; i < 4; i++)
                *(uint4*)&dst[(arow + 32 * i) * STRIDE + acol] = cvt4(av[i]);
#pragma unroll
            for (int i = 0; i < 2; i++)
                *(uint4*)&dst[(BM + arow + 32 * i) * STRIDE + acol] = cvt4(wv[i]);
        }

        // issue LDG for chunk ks+2 (full-chunk slack before use)
        float4 nav[4], nwv[2];
        bool more2 = (ks + 2 < nk);
        if (more2) {
            int koff = (ks + 2) << 5;
#pragma unroll
            for (int i = 0; i < 4; i++)
                nav[i] = *(const float4*)(Ag + (size_t)(32 * i) * K + koff);
#pragma unroll
            for (int i = 0; i < 2; i++)
                nwv[i] = *(const float4*)(Wg + (size_t)(32 * i) * K + koff);
        }

        // consume current buffer via ldmatrix + mma
        uint32_t abase = a_lm + buf * SB;
        uint32_t wbase = w_lm + buf * SB;
#pragma unroll
        for (int kq = 0; kq < 4; kq++) {
            uint32_t a[2][4];
#pragma unroll
            for (int mf = 0; mf < 2; mf++) {
                uint32_t ad = abase + (uint32_t)((mf * 16 * STRIDE + kq * 8) * 4);
                asm volatile(
                    "ldmatrix.sync.aligned.m8n8.x4.shared.b16 {%0,%1,%2,%3}, [%4];"
                    : "=r"(a[mf][0]), "=r"(a[mf][1]), "=r"(a[mf][2]), "=r"(a[mf][3])
                    : "r"(ad));
            }
            uint32_t b[4][2];
#pragma unroll
            for (int np = 0; np < 2; np++) {
                uint32_t r0, r1, r2, r3;
                uint32_t wd = wbase + (uint32_t)((np * 16 * STRIDE + kq * 8) * 4);
                asm volatile(
                    "ldmatrix.sync.aligned.m8n8.x4.shared.b16 {%0,%1,%2,%3}, [%4];"
                    : "=r"(r0), "=r"(r1), "=r"(r2), "=r"(r3)
                    : "r"(wd));
                b[2 * np][0] = r0; b[2 * np + 1][0] = r1;
                b[2 * np][1] = r2; b[2 * np + 1][1] = r3;
            }
#pragma unroll
            for (int nf = 0; nf < 4; nf++)
#pragma unroll
                for (int mf = 0; mf < 2; mf++) {
                    asm volatile(
                        "mma.sync.aligned.m16n8k8.row.col.f32.tf32.tf32.f32 "
                        "{%0,%1,%2,%3}, {%4,%5,%6,%7}, {%8,%9}, {%0,%1,%2,%3};"
                        : "+f"(acc[mf][nf][0]), "+f"(acc[mf][nf][1]),
                          "+f"(acc[mf][nf][2]), "+f"(acc[mf][nf][3])
                        : "r"(a[mf][0]), "r"(a[mf][1]), "r"(a[mf][2]),
                          "r"(a[mf][3]), "r"(b[nf][0]), "r"(b[nf][1]));
                }
        }

        __syncthreads();

        if (more2) {
#pragma unroll
            for (int i = 0; i < 4; i++) av[i] = nav[i];
#pragma unroll
            for (int i = 0; i < 2; i++) wv[i] = nwv[i];
        }
    }

    // epilogue: bias + tanh (+ *log2e)
#pragma unroll
    for (int mf = 0; mf < 2; mf++) {
        int r0 = m0 + wm * 32 + mf * 16 + fr;
#pragma unroll
        for (int nf = 0; nf < 4; nf++) {
            int col = n0 + wn * 32 + nf * 8 + 2 * fc;
            float bb0 = dsc.bias[col];
            float bb1 = dsc.bias[col + 1];
            float v0 = tanhf(acc[mf][nf][0] + bb0);
            float v1 = tanhf(acc[mf][nf][1] + bb1);
            float v2 = tanhf(acc[mf][nf][2] + bb0);
            float v3 = tanhf(acc[mf][nf][3] + bb1);
            if (dsc.mode) { v0 *= LOG2E; v1 *= LOG2E; v2 *= LOG2E; v3 *= LOG2E; }
            *(float2*)&dsc.C[(size_t)r0       * N + col] = make_float2(v0, v1);
            *(float2*)&dsc.C[(size_t)(r0 + 8) * N + col] = make_float2(v2, v3);
        }
    }
}

// ============================================================================
// Attention partial over S/SCH = 32 encoder positions per block.
// ============================================================================
__global__ void __launch_bounds__(128)
dual_attn_partial(const float* __restrict__ out_hs,
                  const float* __restrict__ out_fds,
                  const float* __restrict__ enc,
                  const float* __restrict__ o2p,
                  const float* __restrict__ o3p,
                  float* __restrict__ ps1,
                  float* __restrict__ ps2)
{
    int d  = blockIdx.x * 128 + threadIdx.x;
    int t0 = blockIdx.y * TT;
    int bz = blockIdx.z;
    int b  = bz >> 3;
    int sc = bz & 7;

    float o2[TT], o3[TT], s1[TT], s2[TT];
#pragma unroll
    for (int i = 0; i < TT; i++) {
        int r = b * T_ + t0 + i;
        o2[i] = o2p[r * D_ + d];
        o3[i] = o3p[r * D_ + d];
        s1[i] = 0.f;
        s2[i] = 0.f;
    }

    const int SC = S_ / SCH;   // 32
    size_t base = ((size_t)b * S_ + sc * SC) * D_ + d;

    for (int s = 0; s < SC; s += 4) {
        float hh[4], ff[4], ee[4];
#pragma unroll
        for (int u = 0; u < 4; u++) hh[u] = out_hs [base + u * D_];
#pragma unroll
        for (int u = 0; u < 4; u++) ff[u] = out_fds[base + u * D_];
#pragma unroll
        for (int u = 0; u < 4; u++) ee[u] = enc    [base + u * D_];
        base += 4 * D_;
#pragma unroll
        for (int u = 0; u < 4; u++) {
#pragma unroll
            for (int i = 0; i < TT; i++) {
                float g = fmaf(hh[u], o2[i], ff[u] * o3[i]);
                float ex;
                asm("ex2.approx.f32 %0, %1;" : "=f"(ex) : "f"(g));
                s1[i] += ex;
                s2[i] = fmaf(ex, ee[u], s2[i]);
            }
        }
    }

#pragma unroll
    for (int i = 0; i < TT; i++) {
        size_t idx = (((size_t)(b * T_ + t0 + i)) * SCH + sc) * D_ + d;
        ps1[idx] = s1[i];
        ps2[idx] = s2[i];
    }
}

// ============================================================================
// Finalize: reduce SCH partials (float4), divide, write concat (+attn).
// ============================================================================
__global__ void __launch_bounds__(128)
attn_finalize(const float* __restrict__ ps1,
              const float* __restrict__ ps2,
              const float* __restrict__ outp,
              float* __restrict__ concat,
              float* __restrict__ attn_out)
{
    int d4 = threadIdx.x * 4;
    int r  = blockIdx.z * T_ + blockIdx.y;

    size_t base = ((size_t)r * SCH) * D_ + d4;
    float4 s1 = make_float4(0, 0, 0, 0), s2 = make_float4(0, 0, 0, 0);
#pragma unroll
    for (int sc = 0; sc < SCH; sc++) {
        float4 a = *(const float4*)&ps1[base + (size_t)sc * D_];
        float4 b = *(const float4*)&ps2[base + (size_t)sc * D_];
        s1.x += a.x; s1.y += a.y; s1.z += a.z; s1.w += a.w;
        s2.x += b.x; s2.y += b.y; s2.z += b.z; s2.w += b.w;
    }
    float4 at = make_float4(s2.x / s1.x, s2.y / s1.y, s2.z / s1.z, s2.w / s1.w);
    float4 ov = *(const float4*)&outp[(size_t)r * D_ + d4];
    *(float4*)&concat[(size_t)r * (2 * D_) + d4]      = ov;
    *(float4*)&concat[(size_t)r * (2 * D_) + D_ + d4] = at;
    if (attn_out) *(float4*)&attn_out[(size_t)r * D_ + d4] = at;
}

// ============================================================================
// kernel_launch
// ============================================================================
extern "C" void kernel_launch(void* const* d_in, const int* in_sizes, int n_in,
                              void* d_out, int out_size)
{
    const float* output = (const float*)d_in[0];
    const float* enc    = (const float*)d_in[1];
    const float* z      = (const float*)d_in[2];
    const float* W1 = (const float*)d_in[3];
    const float* b1 = (const float*)d_in[4];
    const float* W2 = (const float*)d_in[5];
    const float* b2 = (const float*)d_in[6];
    const float* W3 = (const float*)d_in[7];
    const float* b3 = (const float*)d_in[8];
    const float* W4 = (const float*)d_in[9];
    const float* b4 = (const float*)d_in[10];

    float *p_hs, *p_fds, *p_o2, *p_o3, *p_s1, *p_s2;
    cudaGetSymbolAddress((void**)&p_hs,  g_out_hs);
    cudaGetSymbolAddress((void**)&p_fds, g_out_fds);
    cudaGetSymbolAddress((void**)&p_o2,  g_o2p);
    cudaGetSymbolAddress((void**)&p_o3,  g_o3p);
    cudaGetSymbolAddress((void**)&p_s1,  g_ps1);
    cudaGetSymbolAddress((void**)&p_s2,  g_ps2);

    float* concat = (float*)d_out;
    const int concat_elems = B_ * T_ * 2 * D_;
    const int attn_elems   = B_ * T_ * D_;
    float* attn_out = (out_size >= concat_elems + attn_elems)
                        ? concat + concat_elems : nullptr;

    cudaFuncSetAttribute(fused_gemm_tf32,
                         cudaFuncAttributeMaxDynamicSharedMemorySize,
                         GEMM_SMEM_BYTES);

    // HEAVY blocks first (K=512), LIGHT lin3 (K=128) LAST so the 12-block
    // overflow beyond 148 SMs lands on light work:
    //   lin1: bids 0-63, lin2: 64-79, lin4: 80-95, lin3: 96-159
    Descs P;
    P.d[0] = { enc,    W1, b1, p_hs,  E_, D_, 0,   0, D_ / BN };
    P.d[1] = { output, W2, b2, p_o2,  D_, D_, 1,  64, D_ / BN };
    P.d[2] = { output, W4, b4, p_o3,  D_, D_, 1,  80, D_ / BN };
    P.d[3] = { z,      W3, b3, p_fds, F_, D_, 0,  96, D_ / BN };

    fused_gemm_tf32<<<160, 256, GEMM_SMEM_BYTES>>>(P);

    dual_attn_partial<<<dim3(D_ / 128, T_ / TT, B_ * SCH), 128>>>(
        p_hs, p_fds, enc, p_o2, p_o3, p_s1, p_s2);

    attn_finalize<<<dim3(1, T_, B_), 128>>>(
        p_s1, p_s2, output, concat, attn_out);
}